// round 15
// baseline (speedup 1.0000x reference)
#include <cuda_runtime.h>
#include <cuda_fp16.h>
#include <cstdint>

#define NTOK     262144     // 32*8192 rows
#define KCODES   512
#define DDIM     64
#define M_TILE   256        // rows per assign CTA
#define A_CTAS   (NTOK / M_TILE)   // 1024
#define A_BLOCKS A_CTAS     // counting-sort blocks == assign CTAs (256 rows each)
#define EPS1     2.5e-2f

// ---------------- scratch (static __device__, allocation-free) ----------------
__device__ int g_idx[NTOK];
__device__ int g_bh[KCODES * A_BLOCKS];      // [k][b]
__device__ int g_bhoff[KCODES * A_BLOCKS];   // [k][b]
__device__ int g_off[KCODES];
__device__ int g_tot[KCODES];
__device__ int g_sorted[NTOK];
__device__ __align__(16) float g_code[KCODES * DDIM];
__device__ __align__(16) __half g_E0[KCODES * DDIM];   // fp16 embedding
__device__ float g_half[KCODES];             // 0.5*||e||^2
__device__ int g_flagN;
__device__ int g_flag[NTOK];

// ---------------- helpers ----------------
__device__ __forceinline__ uint32_t smem_u32(const void* p) {
    uint32_t a;
    asm("{ .reg .u64 t; cvta.to.shared.u64 t, %1; cvt.u32.u64 %0, t; }" : "=r"(a) : "l"(p));
    return a;
}
__device__ __forceinline__ uint32_t packh2(float lo, float hi) {
    __half2 h = __floats2half2_rn(lo, hi);
    return *reinterpret_cast<uint32_t*>(&h);
}
__device__ __forceinline__ void ldsm_x4(uint32_t r[4], uint32_t addr) {
    asm volatile("ldmatrix.sync.aligned.m8n8.x4.shared.b16 {%0,%1,%2,%3}, [%4];"
        : "=r"(r[0]), "=r"(r[1]), "=r"(r[2]), "=r"(r[3]) : "r"(addr));
}
__device__ __forceinline__ void mma_f16(float c[4], const uint32_t a[4],
                                        uint32_t b0, uint32_t b1) {
    asm volatile("mma.sync.aligned.m16n8k16.row.col.f32.f16.f16.f32 "
        "{%0,%1,%2,%3}, {%4,%5,%6,%7}, {%8,%9}, {%0,%1,%2,%3};"
        : "+f"(c[0]), "+f"(c[1]), "+f"(c[2]), "+f"(c[3])
        : "r"(a[0]), "r"(a[1]), "r"(a[2]), "r"(a[3]), "r"(b0), "r"(b1));
}
// branch-free argmax update; ties keep the earlier/lower code
__device__ __forceinline__ void upd(float v, int c, float& b, float& s, int& i) {
    float mn = fminf(v, b);
    s = fmaxf(s, mn);
    i = (v > b) ? c : i;
    b = fmaxf(b, v);
}
// order-preserving encode: max(key) == max score, ties -> lowest code index
__device__ __forceinline__ unsigned long long enc(float s, int idx) {
    uint32_t u = __float_as_uint(s);
    u = (u & 0x80000000u) ? ~u : (u | 0x80000000u);
    return ((unsigned long long)u << 32) | (unsigned long long)(uint32_t)(KCODES - 1 - idx);
}

// assign smem layout (stride-72 halves per row => 144B, conflict-free ldmatrix)
#define A_TILE_B  36864               // 256 rows * 72 * 2B
#define B_TILE_B  73728               // 512 codes * 72 * 2B
#define SM_A      0
#define SM_B      A_TILE_B            // 36864
#define SM_H      (SM_B + B_TILE_B)   // 110592
#define SM_HIST   (SM_H + KCODES * 4) // 112640
#define SM_BYTES  (SM_HIST + KCODES * 4)  // 114688  (x2 CTAs = 224 KB/SM)

#define R_ROWS   16

__global__ void init_flags_kernel() { if (threadIdx.x == 0) g_flagN = 0; }

// ---------------- prep: fp16 embedding + 0.5*||e||^2 ----------------
__global__ void prep_kernel(const float* __restrict__ emb)
{
    __shared__ float part[2];
    const int k = blockIdx.x;       // 512 blocks x 64 threads
    const int d = threadIdx.x;
    float e = emb[k * 64 + d];
    g_E0[k * 64 + d] = __float2half_rn(e);

    float sq = e * e;
    #pragma unroll
    for (int o = 16; o > 0; o >>= 1) sq += __shfl_down_sync(0xffffffffu, sq, o);
    if ((d & 31) == 0) part[d >> 5] = sq;
    __syncthreads();
    if (d == 0) g_half[k] = 0.5f * (part[0] + part[1]);
}

// ---------------- kernel A: single-product fp16 MMA argmin + fused histogram -------
__global__ void __launch_bounds__(512, 2) assign_mma(const float* __restrict__ x)
{
    extern __shared__ __align__(16) char smem[];
    const uint32_t sb = smem_u32(smem);
    float* hbuf  = (float*)(smem + SM_H);
    int*   shist = (int*)  (smem + SM_HIST);

    const int tid  = threadIdx.x;
    const int warp = tid >> 5;      // 0..15
    const int lane = tid & 31;
    const int blk  = blockIdx.x;

    // ---- stage A: x rows -> fp16 (stride 72) ----
    {
        const float4* xs = (const float4*)(x + (size_t)blk * M_TILE * DDIM);
        #pragma unroll
        for (int t = 0; t < 8; ++t) {
            int i = tid + t * 512;            // 4096 float4 total
            float4 v = xs[i];
            int row = i >> 4, grp = i & 15;
            uint32_t off = (uint32_t)row * 144u + (uint32_t)grp * 8u;
            uint2 p0; p0.x = packh2(v.x, v.y); p0.y = packh2(v.z, v.w);
            *reinterpret_cast<uint2*>(smem + SM_A + off) = p0;
        }
    }
    // ---- stage B: fp16 e (stride 72) + half norms + zero hist ----
    {
        const uint2* s0 = (const uint2*)g_E0;
        #pragma unroll
        for (int t = 0; t < 16; ++t) {
            int i = tid + t * 512;            // 8192 uint2
            int code = i >> 4, grp = i & 15;
            uint32_t off = (uint32_t)code * 144u + (uint32_t)grp * 8u;
            *reinterpret_cast<uint2*>(smem + SM_B + off) = s0[i];
        }
        hbuf[tid]  = g_half[tid];
        shist[tid] = 0;
    }
    __syncthreads();

    // ---- load A fragments (resident): 4 ksteps x ldmatrix.x4 ----
    const int lm = lane >> 3, lr = lane & 7;
    uint32_t afr[4][4];
    {
        uint32_t aoff = ((uint32_t)(warp * 16 + lr + (lm & 1) * 8) * 72u
                       + (uint32_t)(lm >> 1) * 8u) * 2u;
        #pragma unroll
        for (int k = 0; k < 4; ++k)
            ldsm_x4(afr[k], sb + SM_A + aoff + k * 32);
    }

    const uint32_t bbase = sb + SM_B + ((uint32_t)lr * 72u + (uint32_t)lm * 8u) * 2u;

    float best0 = -3.0e38f, sec0 = -3.0e38f;
    float best1 = -3.0e38f, sec1 = -3.0e38f;
    int idx0 = 0, idx1 = 0;
    const int q4 = lane & 3;

    // software-pipelined over nt: double-buffered B fragments
    uint32_t Ba[8], Bb[8];
    ldsm_x4(&Ba[0], bbase);
    ldsm_x4(&Ba[4], bbase + 64);

    #pragma unroll 1
    for (int nt = 0; nt < 64; nt += 2) {
        {   // prefetch nt+1
            uint32_t nb = bbase + (uint32_t)(nt + 1) * 1152u;
            ldsm_x4(&Bb[0], nb);
            ldsm_x4(&Bb[4], nb + 64);
        }
        {   // compute nt with Ba
            const int cbase = nt * 8 + 2 * q4;
            float2 h = *reinterpret_cast<const float2*>(hbuf + cbase);
            float c00[4] = {-h.x, -h.y, -h.x, -h.y};
            #pragma unroll
            for (int k = 0; k < 4; ++k)
                mma_f16(c00, afr[k], Ba[2*k], Ba[2*k+1]);
            upd(c00[0], cbase,     best0, sec0, idx0);
            upd(c00[1], cbase + 1, best0, sec0, idx0);
            upd(c00[2], cbase,     best1, sec1, idx1);
            upd(c00[3], cbase + 1, best1, sec1, idx1);
        }
        if (nt + 2 < 64) {   // prefetch nt+2
            uint32_t nb = bbase + (uint32_t)(nt + 2) * 1152u;
            ldsm_x4(&Ba[0], nb);
            ldsm_x4(&Ba[4], nb + 64);
        }
        {   // compute nt+1 with Bb
            const int cbase = (nt + 1) * 8 + 2 * q4;
            float2 h = *reinterpret_cast<const float2*>(hbuf + cbase);
            float c00[4] = {-h.x, -h.y, -h.x, -h.y};
            #pragma unroll
            for (int k = 0; k < 4; ++k)
                mma_f16(c00, afr[k], Bb[2*k], Bb[2*k+1]);
            upd(c00[0], cbase,     best0, sec0, idx0);
            upd(c00[1], cbase + 1, best0, sec0, idx0);
            upd(c00[2], cbase,     best1, sec1, idx1);
            upd(c00[3], cbase + 1, best1, sec1, idx1);
        }
    }

    // merge across quad
    #pragma unroll
    for (int off = 1; off <= 2; off <<= 1) {
        float ob = __shfl_xor_sync(0xffffffffu, best0, off);
        float os = __shfl_xor_sync(0xffffffffu, sec0,  off);
        int   oi = __shfl_xor_sync(0xffffffffu, idx0,  off);
        if (ob > best0 || (ob == best0 && oi < idx0)) {
            sec0 = fmaxf(best0, os); best0 = ob; idx0 = oi;
        } else sec0 = fmaxf(sec0, ob);

        float pb = __shfl_xor_sync(0xffffffffu, best1, off);
        float ps = __shfl_xor_sync(0xffffffffu, sec1,  off);
        int   pi = __shfl_xor_sync(0xffffffffu, idx1,  off);
        if (pb > best1 || (pb == best1 && pi < idx1)) {
            sec1 = fmaxf(best1, ps); best1 = pb; idx1 = pi;
        } else sec1 = fmaxf(sec1, pb);
    }

    if (q4 == 0) {
        const int row0 = blk * M_TILE + warp * 16 + (lane >> 2);
        const int row1 = row0 + 8;
        g_idx[row0] = idx0;
        g_idx[row1] = idx1;
        atomicAdd(&shist[idx0], 1);
        atomicAdd(&shist[idx1], 1);
        if (best0 - sec0 < EPS1) { int p = atomicAdd(&g_flagN, 1); g_flag[p] = row0; }
        if (best1 - sec1 < EPS1) { int p = atomicAdd(&g_flagN, 1); g_flag[p] = row1; }
    }
    __syncthreads();
    g_bh[tid * A_BLOCKS + blk] = shist[tid];
}

// ---------------- recheck v3: exact fp32 argmin, embedding via __ldg (L1/L2) -------
// 512 threads = (row 0..15) x (chunk 0..31 of 16 codes); 16 register accumulators.
// No smem staging of E (it is L2/L1 resident). Fixed order -> deterministic; winner
// via order-encoded u64 atomicMax (ties -> lowest code index).
__global__ void __launch_bounds__(512, 3) recheck_kernel(const float* __restrict__ x,
                                                         const float* __restrict__ emb)
{
    __shared__ float4 sx4[R_ROWS * 17];
    __shared__ unsigned long long sres[R_ROWS];

    const int tid = threadIdx.x;
    const int nflag = g_flagN;
    const int ntile = (nflag + R_ROWS - 1) / R_ROWS;
    if (blockIdx.x >= (unsigned)ntile) return;

    const float4* e4 = (const float4*)emb;

    for (int t = blockIdx.x; t < ntile; t += gridDim.x) {
        __syncthreads();
        if (tid < 256) {   // stage 16 rows (256 float4)
            int row = tid >> 4, grp = tid & 15;
            int fi = t * R_ROWS + row;
            int rid = g_flag[fi < nflag ? fi : 0];
            sx4[row * 17 + grp] = ((const float4*)x)[(size_t)rid * 16 + grp];
        }
        if (tid < R_ROWS) sres[tid] = 0ull;
        __syncthreads();

        const int row = tid & 15;
        const int c0 = (tid >> 4) * 16;      // chunk of 16 codes

        float acc[16];
        #pragma unroll
        for (int j = 0; j < 16; ++j) acc[j] = 0.f;

        #pragma unroll 4
        for (int q = 0; q < 16; ++q) {
            float4 xv = sx4[row * 17 + q];
            #pragma unroll
            for (int j = 0; j < 16; ++j) {
                float4 ev = __ldg(&e4[(c0 + j) * 16 + q]);
                acc[j] += ev.x * xv.x + ev.y * xv.y + ev.z * xv.z + ev.w * xv.w;
            }
        }

        float best = -3.0e38f; int bi = 0;
        #pragma unroll
        for (int j = 0; j < 16; ++j) {
            float v = acc[j] - g_half[c0 + j];
            if (v > best) { best = v; bi = c0 + j; }   // ascending j: first max
        }
        atomicMax(&sres[row], enc(best, bi));
        __syncthreads();

        if (tid < R_ROWS) {
            int fi = t * R_ROWS + tid;
            if (fi < nflag) {
                int rid = g_flag[fi];
                int bi2 = KCODES - 1 - (int)(sres[tid] & 0xffffffffull);
                int old = g_idx[rid];
                if (bi2 != old) {
                    g_idx[rid] = bi2;
                    const int b = rid >> 8;                  // 256 rows per block
                    atomicSub(&g_bh[old * A_BLOCKS + b], 1);
                    atomicAdd(&g_bh[bi2 * A_BLOCKS + b], 1);
                }
            }
        }
    }
}

// ---------------- scan1: per-cluster block-prefix, one warp per cluster ------------
__global__ void scan1_kernel()
{
    const int k = blockIdx.x;
    const int lane = threadIdx.x;
    const int4* src = (const int4*)(g_bh + k * A_BLOCKS + lane * 32);
    int4 v[8];
    int s = 0;
    #pragma unroll
    for (int j = 0; j < 8; ++j) { v[j] = src[j]; s += v[j].x + v[j].y + v[j].z + v[j].w; }
    int run = s;
    #pragma unroll
    for (int off = 1; off < 32; off <<= 1) {
        int t = __shfl_up_sync(0xffffffffu, run, off);
        if (lane >= off) run += t;
    }
    int c = run - s;
    int4* dst = (int4*)(g_bhoff + k * A_BLOCKS + lane * 32);
    #pragma unroll
    for (int j = 0; j < 8; ++j) {
        int4 o;
        o.x = c; c += v[j].x;
        o.y = c; c += v[j].y;
        o.z = c; c += v[j].z;
        o.w = c; c += v[j].w;
        dst[j] = o;
    }
    if (lane == 31) g_tot[k] = run;
}

// ---------------- scan2: global exclusive scan over cluster totals -----------------
__global__ void scan2_kernel()
{
    __shared__ int ts[KCODES];
    const int k = threadIdx.x;
    int tot = g_tot[k];
    ts[k] = tot;
    __syncthreads();
    for (int off = 1; off < KCODES; off <<= 1) {
        int add = (k >= off) ? ts[k - off] : 0;
        __syncthreads();
        ts[k] += add;
        __syncthreads();
    }
    g_off[k] = ts[k] - tot;
}

// ---------------- scatter: stable counting sort (prefetched) ----------------
__global__ void scatter_kernel()
{
    __shared__ int scur[KCODES];
    const int b = blockIdx.x;          // 1024 blocks x 256 rows
    const int lane = threadIdx.x;
    for (int k = lane; k < KCODES; k += 32)
        scur[k] = g_off[k] + g_bhoff[k * A_BLOCKS + b];
    const int base = b * 256;
    int pk[8];
    #pragma unroll
    for (int j = 0; j < 8; ++j) pk[j] = g_idx[base + j * 32 + lane];
    __syncwarp();
    #pragma unroll 1
    for (int j = 0; j < 8; ++j) {
        int n = base + j * 32 + lane;
        int k = pk[j];
        unsigned m = __match_any_sync(0xffffffffu, k);
        unsigned below = m & ((1u << lane) - 1u);
        int pos = scur[k] + __popc(below);
        __syncwarp();
        if (below == 0) scur[k] += __popc(m);
        __syncwarp();
        g_sorted[pos] = n;
    }
}

// ---------------- cluster: per-cluster sum (16 fixed chains) + EMA ----------------
__global__ void __launch_bounds__(1024, 1) cluster_kernel(
    const float* __restrict__ x,
    const float* __restrict__ count_in,
    const float* __restrict__ sum_embed)
{
    __shared__ float part[16][DDIM];
    const int k = blockIdx.x;
    const int d = threadIdx.x & 63;
    const int s = threadIdx.x >> 6;
    const int start = g_off[k];
    const int cnt   = g_tot[k];
    const int q  = (cnt + 15) >> 4;
    const int i0 = s * q;
    int i1 = i0 + q; if (i1 > cnt) i1 = cnt;

    float a0 = 0.f, a1 = 0.f, a2 = 0.f, a3 = 0.f;
    int i = i0;
    for (; i + 4 <= i1; i += 4) {
        int r0 = g_sorted[start + i];
        int r1 = g_sorted[start + i + 1];
        int r2 = g_sorted[start + i + 2];
        int r3 = g_sorted[start + i + 3];
        a0 += x[(size_t)r0 * 64 + d];
        a1 += x[(size_t)r1 * 64 + d];
        a2 += x[(size_t)r2 * 64 + d];
        a3 += x[(size_t)r3 * 64 + d];
    }
    for (; i < i1; ++i) a0 += x[(size_t)g_sorted[start + i] * 64 + d];
    part[s][d] = (a0 + a1) + (a2 + a3);
    __syncthreads();

    if (s == 0) {
        float sum = (((part[0][d] + part[1][d]) + (part[2][d] + part[3][d]))
                  +  ((part[4][d] + part[5][d]) + (part[6][d] + part[7][d])))
                  + (((part[8][d] + part[9][d]) + (part[10][d] + part[11][d]))
                  +  ((part[12][d] + part[13][d]) + (part[14][d] + part[15][d])));
        float sev = sum_embed[k * 64 + d];
        float ns  = sev + 0.01f * (sum - sev);
        float cv  = count_in[k];
        float cn  = cv + 0.01f * ((float)cnt - cv);
        if (cn < 1.0f) cn = 1.0f;
        g_code[k * 64 + d] = ns / cn;
    }
}

// ---------------- gather ----------------
__global__ void gather_kernel(float4* __restrict__ out)
{
    const int total = NTOK * 16;
    for (int id = blockIdx.x * blockDim.x + threadIdx.x; id < total;
         id += gridDim.x * blockDim.x) {
        int row = id >> 4;
        int col = id & 15;
        int k = g_idx[row];
        out[id] = ((const float4*)g_code)[k * 16 + col];
    }
}

// ---------------- launch ----------------
extern "C" void kernel_launch(void* const* d_in, const int* in_sizes, int n_in,
                              void* d_out, int out_size)
{
    (void)in_sizes; (void)n_in; (void)out_size;
    const float* x         = (const float*)d_in[0];
    const float* emb       = (const float*)d_in[1];
    const float* count     = (const float*)d_in[2];
    const float* sum_embed = (const float*)d_in[3];

    cudaFuncSetAttribute(assign_mma,
                         cudaFuncAttributeMaxDynamicSharedMemorySize, SM_BYTES);

    prep_kernel<<<KCODES, 64>>>(emb);               // #1
    init_flags_kernel<<<1, 32>>>();                 // #2
    assign_mma<<<A_CTAS, 512, SM_BYTES>>>(x);       // #3
    recheck_kernel<<<256, 512>>>(x, emb);           // #4  <-- ncu capture slot
    scan1_kernel<<<KCODES, 32>>>();
    scan2_kernel<<<1, KCODES>>>();
    scatter_kernel<<<A_BLOCKS, 32>>>();
    cluster_kernel<<<KCODES, 1024>>>(x, count, sum_embed);
    gather_kernel<<<4096, 256>>>((float4*)d_out);
}

// round 16
// speedup vs baseline: 1.0624x; 1.0624x over previous
#include <cuda_runtime.h>
#include <cuda_fp16.h>
#include <cstdint>

#define NTOK     262144     // 32*8192 rows
#define KCODES   512
#define DDIM     64
#define M_TILE   256        // rows per assign CTA
#define A_CTAS   (NTOK / M_TILE)   // 1024
#define A_BLOCKS A_CTAS     // counting-sort blocks == assign CTAs (256 rows each)
#define EPS1     2.5e-2f

// ---------------- scratch (static __device__, allocation-free) ----------------
__device__ int g_idx[NTOK];
__device__ int g_bh[KCODES * A_BLOCKS];      // [k][b]
__device__ int g_bhoff[KCODES * A_BLOCKS];   // [k][b]
__device__ int g_off[KCODES];
__device__ int g_tot[KCODES];
__device__ int g_sorted[NTOK];
__device__ __align__(16) float g_code[KCODES * DDIM];
__device__ __align__(16) __half g_E0[KCODES * DDIM];   // fp16 embedding
__device__ float g_half[KCODES];             // 0.5*||e||^2
__device__ int g_flagN;
__device__ int g_flag[NTOK];

// ---------------- helpers ----------------
__device__ __forceinline__ uint32_t smem_u32(const void* p) {
    uint32_t a;
    asm("{ .reg .u64 t; cvta.to.shared.u64 t, %1; cvt.u32.u64 %0, t; }" : "=r"(a) : "l"(p));
    return a;
}
__device__ __forceinline__ uint32_t packh2(float lo, float hi) {
    __half2 h = __floats2half2_rn(lo, hi);
    return *reinterpret_cast<uint32_t*>(&h);
}
__device__ __forceinline__ void ldsm_x4(uint32_t r[4], uint32_t addr) {
    asm volatile("ldmatrix.sync.aligned.m8n8.x4.shared.b16 {%0,%1,%2,%3}, [%4];"
        : "=r"(r[0]), "=r"(r[1]), "=r"(r[2]), "=r"(r[3]) : "r"(addr));
}
__device__ __forceinline__ void mma_f16(float c[4], const uint32_t a[4],
                                        uint32_t b0, uint32_t b1) {
    asm volatile("mma.sync.aligned.m16n8k16.row.col.f32.f16.f16.f32 "
        "{%0,%1,%2,%3}, {%4,%5,%6,%7}, {%8,%9}, {%0,%1,%2,%3};"
        : "+f"(c[0]), "+f"(c[1]), "+f"(c[2]), "+f"(c[3])
        : "r"(a[0]), "r"(a[1]), "r"(a[2]), "r"(a[3]), "r"(b0), "r"(b1));
}
// branch-free argmax update; ties keep the earlier/lower code
__device__ __forceinline__ void upd(float v, int c, float& b, float& s, int& i) {
    float mn = fminf(v, b);
    s = fmaxf(s, mn);
    i = (v > b) ? c : i;
    b = fmaxf(b, v);
}
// order-preserving encode: max(key) == max score, ties -> lowest code index
__device__ __forceinline__ unsigned long long enc(float s, int idx) {
    uint32_t u = __float_as_uint(s);
    u = (u & 0x80000000u) ? ~u : (u | 0x80000000u);
    return ((unsigned long long)u << 32) | (unsigned long long)(uint32_t)(KCODES - 1 - idx);
}

// assign smem layout (stride-72 halves per row => 144B, conflict-free ldmatrix)
#define A_TILE_B  36864               // 256 rows * 72 * 2B
#define B_TILE_B  73728               // 512 codes * 72 * 2B
#define SM_A      0
#define SM_B      A_TILE_B            // 36864
#define SM_H      (SM_B + B_TILE_B)   // 110592
#define SM_HIST   (SM_H + KCODES * 4) // 112640
#define SM_BYTES  (SM_HIST + KCODES * 4)  // 114688  (x2 CTAs = 224 KB/SM)

// recheck smem layout
#define R_ROWS   16
#define RC_E     0                          // 512*64 fp32 = 131072
#define RC_X     131072                     // 16 rows * 17 float4 = 4352
#define RC_H     (RC_X + 4352)              // 135424: 512 fp32 = 2048
#define RC_R     (RC_H + 2048)              // 137472: 16 u64 = 128
#define RC_BYTES (RC_R + 128)               // 137600

// ---------------- prep: fp16 embedding + 0.5*||e||^2 + flag init ----------------
__global__ void prep_kernel(const float* __restrict__ emb)
{
    __shared__ float part[2];
    const int k = blockIdx.x;       // 512 blocks x 64 threads
    const int d = threadIdx.x;
    float e = emb[k * 64 + d];
    g_E0[k * 64 + d] = __float2half_rn(e);

    float sq = e * e;
    #pragma unroll
    for (int o = 16; o > 0; o >>= 1) sq += __shfl_down_sync(0xffffffffu, sq, o);
    if ((d & 31) == 0) part[d >> 5] = sq;
    __syncthreads();
    if (d == 0) g_half[k] = 0.5f * (part[0] + part[1]);
    if (k == 0 && d == 0) g_flagN = 0;
}

// ---------------- kernel A: single-product fp16 MMA argmin + fused histogram -------
__global__ void __launch_bounds__(512, 2) assign_mma(const float* __restrict__ x)
{
    extern __shared__ __align__(16) char smem[];
    const uint32_t sb = smem_u32(smem);
    float* hbuf  = (float*)(smem + SM_H);
    int*   shist = (int*)  (smem + SM_HIST);

    const int tid  = threadIdx.x;
    const int warp = tid >> 5;      // 0..15
    const int lane = tid & 31;
    const int blk  = blockIdx.x;

    // ---- stage A: x rows -> fp16 (stride 72) ----
    {
        const float4* xs = (const float4*)(x + (size_t)blk * M_TILE * DDIM);
        #pragma unroll
        for (int t = 0; t < 8; ++t) {
            int i = tid + t * 512;            // 4096 float4 total
            float4 v = xs[i];
            int row = i >> 4, grp = i & 15;
            uint32_t off = (uint32_t)row * 144u + (uint32_t)grp * 8u;
            uint2 p0; p0.x = packh2(v.x, v.y); p0.y = packh2(v.z, v.w);
            *reinterpret_cast<uint2*>(smem + SM_A + off) = p0;
        }
    }
    // ---- stage B: fp16 e (stride 72) + half norms + zero hist ----
    {
        const uint2* s0 = (const uint2*)g_E0;
        #pragma unroll
        for (int t = 0; t < 16; ++t) {
            int i = tid + t * 512;            // 8192 uint2
            int code = i >> 4, grp = i & 15;
            uint32_t off = (uint32_t)code * 144u + (uint32_t)grp * 8u;
            *reinterpret_cast<uint2*>(smem + SM_B + off) = s0[i];
        }
        hbuf[tid]  = g_half[tid];
        shist[tid] = 0;
    }
    __syncthreads();

    // ---- load A fragments (resident): 4 ksteps x ldmatrix.x4 ----
    const int lm = lane >> 3, lr = lane & 7;
    uint32_t afr[4][4];
    {
        uint32_t aoff = ((uint32_t)(warp * 16 + lr + (lm & 1) * 8) * 72u
                       + (uint32_t)(lm >> 1) * 8u) * 2u;
        #pragma unroll
        for (int k = 0; k < 4; ++k)
            ldsm_x4(afr[k], sb + SM_A + aoff + k * 32);
    }

    const uint32_t bbase = sb + SM_B + ((uint32_t)lr * 72u + (uint32_t)lm * 8u) * 2u;

    float best0 = -3.0e38f, sec0 = -3.0e38f;
    float best1 = -3.0e38f, sec1 = -3.0e38f;
    int idx0 = 0, idx1 = 0;
    const int q4 = lane & 3;

    // software-pipelined over nt: double-buffered B fragments
    uint32_t Ba[8], Bb[8];
    ldsm_x4(&Ba[0], bbase);
    ldsm_x4(&Ba[4], bbase + 64);

    #pragma unroll 1
    for (int nt = 0; nt < 64; nt += 2) {
        {   // prefetch nt+1
            uint32_t nb = bbase + (uint32_t)(nt + 1) * 1152u;
            ldsm_x4(&Bb[0], nb);
            ldsm_x4(&Bb[4], nb + 64);
        }
        {   // compute nt with Ba
            const int cbase = nt * 8 + 2 * q4;
            float2 h = *reinterpret_cast<const float2*>(hbuf + cbase);
            float c00[4] = {-h.x, -h.y, -h.x, -h.y};
            #pragma unroll
            for (int k = 0; k < 4; ++k)
                mma_f16(c00, afr[k], Ba[2*k], Ba[2*k+1]);
            upd(c00[0], cbase,     best0, sec0, idx0);
            upd(c00[1], cbase + 1, best0, sec0, idx0);
            upd(c00[2], cbase,     best1, sec1, idx1);
            upd(c00[3], cbase + 1, best1, sec1, idx1);
        }
        if (nt + 2 < 64) {   // prefetch nt+2
            uint32_t nb = bbase + (uint32_t)(nt + 2) * 1152u;
            ldsm_x4(&Ba[0], nb);
            ldsm_x4(&Ba[4], nb + 64);
        }
        {   // compute nt+1 with Bb
            const int cbase = (nt + 1) * 8 + 2 * q4;
            float2 h = *reinterpret_cast<const float2*>(hbuf + cbase);
            float c00[4] = {-h.x, -h.y, -h.x, -h.y};
            #pragma unroll
            for (int k = 0; k < 4; ++k)
                mma_f16(c00, afr[k], Bb[2*k], Bb[2*k+1]);
            upd(c00[0], cbase,     best0, sec0, idx0);
            upd(c00[1], cbase + 1, best0, sec0, idx0);
            upd(c00[2], cbase,     best1, sec1, idx1);
            upd(c00[3], cbase + 1, best1, sec1, idx1);
        }
    }

    // merge across quad
    #pragma unroll
    for (int off = 1; off <= 2; off <<= 1) {
        float ob = __shfl_xor_sync(0xffffffffu, best0, off);
        float os = __shfl_xor_sync(0xffffffffu, sec0,  off);
        int   oi = __shfl_xor_sync(0xffffffffu, idx0,  off);
        if (ob > best0 || (ob == best0 && oi < idx0)) {
            sec0 = fmaxf(best0, os); best0 = ob; idx0 = oi;
        } else sec0 = fmaxf(sec0, ob);

        float pb = __shfl_xor_sync(0xffffffffu, best1, off);
        float ps = __shfl_xor_sync(0xffffffffu, sec1,  off);
        int   pi = __shfl_xor_sync(0xffffffffu, idx1,  off);
        if (pb > best1 || (pb == best1 && pi < idx1)) {
            sec1 = fmaxf(best1, ps); best1 = pb; idx1 = pi;
        } else sec1 = fmaxf(sec1, pb);
    }

    if (q4 == 0) {
        const int row0 = blk * M_TILE + warp * 16 + (lane >> 2);
        const int row1 = row0 + 8;
        g_idx[row0] = idx0;
        g_idx[row1] = idx1;
        atomicAdd(&shist[idx0], 1);
        atomicAdd(&shist[idx1], 1);
        if (best0 - sec0 < EPS1) { int p = atomicAdd(&g_flagN, 1); g_flag[p] = row0; }
        if (best1 - sec1 < EPS1) { int p = atomicAdd(&g_flagN, 1); g_flag[p] = row1; }
    }
    __syncthreads();
    g_bh[tid * A_BLOCKS + blk] = shist[tid];
}

// ---------------- recheck: exact fp32 argmin, 16 flagged rows per block ------------
// (R14-proven version) 512 threads = (row 0..15) x (chunk 0..31 of 16 codes);
// 16 register accumulators. Fixed order -> deterministic; winner via order-encoded
// u64 atomicMax (ties -> lowest code index).
__global__ void __launch_bounds__(512, 1) recheck_kernel(const float* __restrict__ x,
                                                         const float* __restrict__ emb)
{
    extern __shared__ __align__(16) char smem[];
    float4* se4 = (float4*)(smem + RC_E);
    float4* sx4 = (float4*)(smem + RC_X);    // stride 17 float4 per row
    float*  sh  = (float*) (smem + RC_H);
    unsigned long long* sres = (unsigned long long*)(smem + RC_R);

    const int tid = threadIdx.x;
    const int nflag = g_flagN;
    const int ntile = (nflag + R_ROWS - 1) / R_ROWS;
    if (blockIdx.x >= (unsigned)ntile) return;

    {
        const float4* e4 = (const float4*)emb;
        #pragma unroll 4
        for (int t = 0; t < 16; ++t) se4[tid + t * 512] = e4[tid + t * 512];
        sh[tid] = g_half[tid];
    }

    for (int t = blockIdx.x; t < ntile; t += gridDim.x) {
        __syncthreads();
        if (tid < 256) {   // stage 16 rows (256 float4)
            int row = tid >> 4, grp = tid & 15;
            int fi = t * R_ROWS + row;
            int rid = g_flag[fi < nflag ? fi : 0];
            sx4[row * 17 + grp] = ((const float4*)x)[(size_t)rid * 16 + grp];
        }
        if (tid < R_ROWS) sres[tid] = 0ull;
        __syncthreads();

        const int row = tid & 15;
        const int c0 = (tid >> 4) * 16;      // chunk of 16 codes

        float acc[16];
        #pragma unroll
        for (int j = 0; j < 16; ++j) acc[j] = 0.f;

        #pragma unroll 4
        for (int q = 0; q < 16; ++q) {
            float4 xv = sx4[row * 17 + q];
            #pragma unroll
            for (int j = 0; j < 16; ++j) {
                float4 ev = se4[(c0 + j) * 16 + q];
                acc[j] += ev.x * xv.x + ev.y * xv.y + ev.z * xv.z + ev.w * xv.w;
            }
        }

        float best = -3.0e38f; int bi = 0;
        #pragma unroll
        for (int j = 0; j < 16; ++j) {
            float v = acc[j] - sh[c0 + j];
            if (v > best) { best = v; bi = c0 + j; }   // ascending j: first max
        }
        atomicMax(&sres[row], enc(best, bi));
        __syncthreads();

        if (tid < R_ROWS) {
            int fi = t * R_ROWS + tid;
            if (fi < nflag) {
                int rid = g_flag[fi];
                int bi2 = KCODES - 1 - (int)(sres[tid] & 0xffffffffull);
                int old = g_idx[rid];
                if (bi2 != old) {
                    g_idx[rid] = bi2;
                    const int b = rid >> 8;                  // 256 rows per block
                    atomicSub(&g_bh[old * A_BLOCKS + b], 1);
                    atomicAdd(&g_bh[bi2 * A_BLOCKS + b], 1);
                }
            }
        }
    }
}

// ---------------- scan1: per-cluster block-prefix, one warp per cluster ------------
__global__ void scan1_kernel()
{
    const int k = blockIdx.x;
    const int lane = threadIdx.x;
    const int4* src = (const int4*)(g_bh + k * A_BLOCKS + lane * 32);
    int4 v[8];
    int s = 0;
    #pragma unroll
    for (int j = 0; j < 8; ++j) { v[j] = src[j]; s += v[j].x + v[j].y + v[j].z + v[j].w; }
    int run = s;
    #pragma unroll
    for (int off = 1; off < 32; off <<= 1) {
        int t = __shfl_up_sync(0xffffffffu, run, off);
        if (lane >= off) run += t;
    }
    int c = run - s;
    int4* dst = (int4*)(g_bhoff + k * A_BLOCKS + lane * 32);
    #pragma unroll
    for (int j = 0; j < 8; ++j) {
        int4 o;
        o.x = c; c += v[j].x;
        o.y = c; c += v[j].y;
        o.z = c; c += v[j].z;
        o.w = c; c += v[j].w;
        dst[j] = o;
    }
    if (lane == 31) g_tot[k] = run;
}

// ---------------- scatter: stable counting sort + local global-offset scan ---------
// Each warp computes the full 512-cluster exclusive scan of g_tot itself (needs all
// offsets anyway); block 0 also publishes g_off for cluster_kernel.
__global__ void scatter_kernel()
{
    __shared__ int scur[KCODES];
    const int b = blockIdx.x;          // 1024 blocks x 256 rows
    const int lane = threadIdx.x;

    // local exclusive scan of g_tot: lane handles clusters [lane*16, lane*16+16)
    int tv[16];
    {
        const int4* tp = (const int4*)(g_tot + lane * 16);
        int4 t0 = tp[0], t1 = tp[1], t2 = tp[2], t3 = tp[3];
        tv[0]=t0.x; tv[1]=t0.y; tv[2]=t0.z; tv[3]=t0.w;
        tv[4]=t1.x; tv[5]=t1.y; tv[6]=t1.z; tv[7]=t1.w;
        tv[8]=t2.x; tv[9]=t2.y; tv[10]=t2.z; tv[11]=t2.w;
        tv[12]=t3.x; tv[13]=t3.y; tv[14]=t3.z; tv[15]=t3.w;
    }
    int lsum = 0;
    #pragma unroll
    for (int j = 0; j < 16; ++j) lsum += tv[j];
    int run = lsum;
    #pragma unroll
    for (int off = 1; off < 32; off <<= 1) {
        int t = __shfl_up_sync(0xffffffffu, run, off);
        if (lane >= off) run += t;
    }
    int c = run - lsum;                 // exclusive prefix at cluster lane*16
    #pragma unroll
    for (int j = 0; j < 16; ++j) {
        int k = lane * 16 + j;
        scur[k] = c + g_bhoff[k * A_BLOCKS + b];
        if (b == 0) g_off[k] = c;       // publish for cluster_kernel
        c += tv[j];
    }
    __syncwarp();

    const int base = b * 256;
    int pk[8];
    #pragma unroll
    for (int j = 0; j < 8; ++j) pk[j] = g_idx[base + j * 32 + lane];
    __syncwarp();
    #pragma unroll 1
    for (int j = 0; j < 8; ++j) {
        int n = base + j * 32 + lane;
        int k = pk[j];
        unsigned m = __match_any_sync(0xffffffffu, k);
        unsigned below = m & ((1u << lane) - 1u);
        int pos = scur[k] + __popc(below);
        __syncwarp();
        if (below == 0) scur[k] += __popc(m);
        __syncwarp();
        g_sorted[pos] = n;
    }
}

// ---------------- cluster: per-cluster sum (16 fixed chains) + EMA ----------------
__global__ void __launch_bounds__(1024, 1) cluster_kernel(
    const float* __restrict__ x,
    const float* __restrict__ count_in,
    const float* __restrict__ sum_embed)
{
    __shared__ float part[16][DDIM];
    const int k = blockIdx.x;
    const int d = threadIdx.x & 63;
    const int s = threadIdx.x >> 6;
    const int start = g_off[k];
    const int cnt   = g_tot[k];
    const int q  = (cnt + 15) >> 4;
    const int i0 = s * q;
    int i1 = i0 + q; if (i1 > cnt) i1 = cnt;

    float a0 = 0.f, a1 = 0.f, a2 = 0.f, a3 = 0.f;
    int i = i0;
    for (; i + 4 <= i1; i += 4) {
        int r0 = g_sorted[start + i];
        int r1 = g_sorted[start + i + 1];
        int r2 = g_sorted[start + i + 2];
        int r3 = g_sorted[start + i + 3];
        a0 += x[(size_t)r0 * 64 + d];
        a1 += x[(size_t)r1 * 64 + d];
        a2 += x[(size_t)r2 * 64 + d];
        a3 += x[(size_t)r3 * 64 + d];
    }
    for (; i < i1; ++i) a0 += x[(size_t)g_sorted[start + i] * 64 + d];
    part[s][d] = (a0 + a1) + (a2 + a3);
    __syncthreads();

    if (s == 0) {
        float sum = (((part[0][d] + part[1][d]) + (part[2][d] + part[3][d]))
                  +  ((part[4][d] + part[5][d]) + (part[6][d] + part[7][d])))
                  + (((part[8][d] + part[9][d]) + (part[10][d] + part[11][d]))
                  +  ((part[12][d] + part[13][d]) + (part[14][d] + part[15][d])));
        float sev = sum_embed[k * 64 + d];
        float ns  = sev + 0.01f * (sum - sev);
        float cv  = count_in[k];
        float cn  = cv + 0.01f * ((float)cnt - cv);
        if (cn < 1.0f) cn = 1.0f;
        g_code[k * 64 + d] = ns / cn;
    }
}

// ---------------- gather ----------------
__global__ void gather_kernel(float4* __restrict__ out)
{
    const int total = NTOK * 16;
    for (int id = blockIdx.x * blockDim.x + threadIdx.x; id < total;
         id += gridDim.x * blockDim.x) {
        int row = id >> 4;
        int col = id & 15;
        int k = g_idx[row];
        out[id] = ((const float4*)g_code)[k * 16 + col];
    }
}

// ---------------- launch ----------------
extern "C" void kernel_launch(void* const* d_in, const int* in_sizes, int n_in,
                              void* d_out, int out_size)
{
    (void)in_sizes; (void)n_in; (void)out_size;
    const float* x         = (const float*)d_in[0];
    const float* emb       = (const float*)d_in[1];
    const float* count     = (const float*)d_in[2];
    const float* sum_embed = (const float*)d_in[3];

    cudaFuncSetAttribute(assign_mma,
                         cudaFuncAttributeMaxDynamicSharedMemorySize, SM_BYTES);
    cudaFuncSetAttribute(recheck_kernel,
                         cudaFuncAttributeMaxDynamicSharedMemorySize, RC_BYTES);

    prep_kernel<<<KCODES, 64>>>(emb);               // #1
    assign_mma<<<A_CTAS, 512, SM_BYTES>>>(x);       // #2
    recheck_kernel<<<256, 512, RC_BYTES>>>(x, emb); // #3
    scan1_kernel<<<KCODES, 32>>>();                 // #4  <-- ncu capture slot
    scatter_kernel<<<A_BLOCKS, 32>>>();
    cluster_kernel<<<KCODES, 1024>>>(x, count, sum_embed);
    gather_kernel<<<4096, 256>>>((float4*)d_out);
}

// round 17
// speedup vs baseline: 1.0667x; 1.0040x over previous
#include <cuda_runtime.h>
#include <cuda_fp16.h>
#include <cstdint>

#define NTOK     262144     // 32*8192 rows
#define KCODES   512
#define DDIM     64
#define M_TILE   256        // rows per assign CTA
#define A_CTAS   (NTOK / M_TILE)   // 1024
#define A_BLOCKS A_CTAS     // counting-sort blocks == assign CTAs (256 rows each)
#define EPS1     2.5e-2f

// ---------------- scratch (static __device__, allocation-free) ----------------
__device__ int g_idx[NTOK];
__device__ int g_bh[KCODES * A_BLOCKS];      // [k][b]
__device__ int g_bhoff[KCODES * A_BLOCKS];   // [k][b]
__device__ int g_off[KCODES];
__device__ int g_tot[KCODES];
__device__ int g_sorted[NTOK];
__device__ __align__(16) float g_code[KCODES * DDIM];
__device__ __align__(16) __half g_E0[KCODES * DDIM];   // fp16 embedding
__device__ float g_nhalf[KCODES];            // NEGATED 0.5*||e||^2
__device__ int g_flagN;
__device__ int g_flag[NTOK];

// ---------------- helpers ----------------
__device__ __forceinline__ uint32_t smem_u32(const void* p) {
    uint32_t a;
    asm("{ .reg .u64 t; cvta.to.shared.u64 t, %1; cvt.u32.u64 %0, t; }" : "=r"(a) : "l"(p));
    return a;
}
__device__ __forceinline__ uint32_t packh2(float lo, float hi) {
    __half2 h = __floats2half2_rn(lo, hi);
    return *reinterpret_cast<uint32_t*>(&h);
}
__device__ __forceinline__ void ldsm_x4(uint32_t r[4], uint32_t addr) {
    asm volatile("ldmatrix.sync.aligned.m8n8.x4.shared.b16 {%0,%1,%2,%3}, [%4];"
        : "=r"(r[0]), "=r"(r[1]), "=r"(r[2]), "=r"(r[3]) : "r"(addr));
}
__device__ __forceinline__ void mma_f16(float c[4], const uint32_t a[4],
                                        uint32_t b0, uint32_t b1) {
    asm volatile("mma.sync.aligned.m16n8k16.row.col.f32.f16.f16.f32 "
        "{%0,%1,%2,%3}, {%4,%5,%6,%7}, {%8,%9}, {%0,%1,%2,%3};"
        : "+f"(c[0]), "+f"(c[1]), "+f"(c[2]), "+f"(c[3])
        : "r"(a[0]), "r"(a[1]), "r"(a[2]), "r"(a[3]), "r"(b0), "r"(b1));
}
// branch-free argmax update; ties keep the earlier/lower code
__device__ __forceinline__ void upd(float v, int c, float& b, float& s, int& i) {
    float mn = fminf(v, b);
    s = fmaxf(s, mn);
    i = (v > b) ? c : i;
    b = fmaxf(b, v);
}
// order-preserving encode: max(key) == max score, ties -> lowest code index
__device__ __forceinline__ unsigned long long enc(float s, int idx) {
    uint32_t u = __float_as_uint(s);
    u = (u & 0x80000000u) ? ~u : (u | 0x80000000u);
    return ((unsigned long long)u << 32) | (unsigned long long)(uint32_t)(KCODES - 1 - idx);
}

// assign smem layout (stride-72 halves per row => 144B, conflict-free ldmatrix)
#define A_TILE_B  36864               // 256 rows * 72 * 2B
#define B_TILE_B  73728               // 512 codes * 72 * 2B
#define SM_A      0
#define SM_B      A_TILE_B            // 36864
#define SM_H      (SM_B + B_TILE_B)   // 110592
#define SM_HIST   (SM_H + KCODES * 4) // 112640
#define SM_BYTES  (SM_HIST + KCODES * 4)  // 114688  (x2 CTAs = 224 KB/SM)

// recheck smem layout
#define R_ROWS   16
#define RC_E     0                          // 512*64 fp32 = 131072
#define RC_X     131072                     // 16 rows * 17 float4 = 4352
#define RC_H     (RC_X + 4352)              // 135424: 512 fp32 = 2048
#define RC_R     (RC_H + 2048)              // 137472: 16 u64 = 128
#define RC_BYTES (RC_R + 128)               // 137600

// ---------------- prep: fp16 embedding + negated 0.5*||e||^2 + flag init -----------
__global__ void prep_kernel(const float* __restrict__ emb)
{
    __shared__ float part[2];
    const int k = blockIdx.x;       // 512 blocks x 64 threads
    const int d = threadIdx.x;
    float e = emb[k * 64 + d];
    g_E0[k * 64 + d] = __float2half_rn(e);

    float sq = e * e;
    #pragma unroll
    for (int o = 16; o > 0; o >>= 1) sq += __shfl_down_sync(0xffffffffu, sq, o);
    if ((d & 31) == 0) part[d >> 5] = sq;
    __syncthreads();
    if (d == 0) g_nhalf[k] = -0.5f * (part[0] + part[1]);
    if (k == 0 && d == 0) g_flagN = 0;
}

// ---------------- kernel A: single-product fp16 MMA argmin + fused histogram -------
__global__ void __launch_bounds__(512, 2) assign_mma(const float* __restrict__ x)
{
    extern __shared__ __align__(16) char smem[];
    const uint32_t sb = smem_u32(smem);
    float* hbuf  = (float*)(smem + SM_H);     // holds NEGATED half norms
    int*   shist = (int*)  (smem + SM_HIST);

    const int tid  = threadIdx.x;
    const int warp = tid >> 5;      // 0..15
    const int lane = tid & 31;
    const int blk  = blockIdx.x;

    // ---- stage A: x rows -> fp16 (stride 72) ----
    {
        const float4* xs = (const float4*)(x + (size_t)blk * M_TILE * DDIM);
        #pragma unroll
        for (int t = 0; t < 8; ++t) {
            int i = tid + t * 512;            // 4096 float4 total
            float4 v = xs[i];
            int row = i >> 4, grp = i & 15;
            uint32_t off = (uint32_t)row * 144u + (uint32_t)grp * 8u;
            uint2 p0; p0.x = packh2(v.x, v.y); p0.y = packh2(v.z, v.w);
            *reinterpret_cast<uint2*>(smem + SM_A + off) = p0;
        }
    }
    // ---- stage B: fp16 e (stride 72) + negated half norms + zero hist ----
    {
        const uint2* s0 = (const uint2*)g_E0;
        #pragma unroll
        for (int t = 0; t < 16; ++t) {
            int i = tid + t * 512;            // 8192 uint2
            int code = i >> 4, grp = i & 15;
            uint32_t off = (uint32_t)code * 144u + (uint32_t)grp * 8u;
            *reinterpret_cast<uint2*>(smem + SM_B + off) = s0[i];
        }
        hbuf[tid]  = g_nhalf[tid];
        shist[tid] = 0;
    }
    __syncthreads();

    // ---- load A fragments (resident): 4 ksteps x ldmatrix.x4 ----
    const int lm = lane >> 3, lr = lane & 7;
    uint32_t afr[4][4];
    {
        uint32_t aoff = ((uint32_t)(warp * 16 + lr + (lm & 1) * 8) * 72u
                       + (uint32_t)(lm >> 1) * 8u) * 2u;
        #pragma unroll
        for (int k = 0; k < 4; ++k)
            ldsm_x4(afr[k], sb + SM_A + aoff + k * 32);
    }

    const uint32_t bbase = sb + SM_B + ((uint32_t)lr * 72u + (uint32_t)lm * 8u) * 2u;

    float best0 = -3.0e38f, sec0 = -3.0e38f;
    float best1 = -3.0e38f, sec1 = -3.0e38f;
    int idx0 = 0, idx1 = 0;
    const int q4 = lane & 3;

    // software-pipelined over nt: double-buffered B fragments
    uint32_t Ba[8], Bb[8];
    ldsm_x4(&Ba[0], bbase);
    ldsm_x4(&Ba[4], bbase + 64);

    #pragma unroll 1
    for (int nt = 0; nt < 64; nt += 2) {
        {   // prefetch nt+1 (always valid)
            uint32_t nb = bbase + (uint32_t)(nt + 1) * 1152u;
            ldsm_x4(&Bb[0], nb);
            ldsm_x4(&Bb[4], nb + 64);
        }
        {   // compute nt with Ba (init = negated half norms; no FNEG needed)
            const int cbase = nt * 8 + 2 * q4;
            float2 h = *reinterpret_cast<const float2*>(hbuf + cbase);
            float c00[4] = {h.x, h.y, h.x, h.y};
            #pragma unroll
            for (int k = 0; k < 4; ++k)
                mma_f16(c00, afr[k], Ba[2*k], Ba[2*k+1]);
            upd(c00[0], cbase,     best0, sec0, idx0);
            upd(c00[1], cbase + 1, best0, sec0, idx0);
            upd(c00[2], cbase,     best1, sec1, idx1);
            upd(c00[3], cbase + 1, best1, sec1, idx1);
        }
        {   // prefetch nt+2, branch-free (clamped index; last prefetch is unused)
            int pf = (nt + 2 < 64) ? (nt + 2) : 62;
            uint32_t nb = bbase + (uint32_t)pf * 1152u;
            ldsm_x4(&Ba[0], nb);
            ldsm_x4(&Ba[4], nb + 64);
        }
        {   // compute nt+1 with Bb
            const int cbase = (nt + 1) * 8 + 2 * q4;
            float2 h = *reinterpret_cast<const float2*>(hbuf + cbase);
            float c00[4] = {h.x, h.y, h.x, h.y};
            #pragma unroll
            for (int k = 0; k < 4; ++k)
                mma_f16(c00, afr[k], Bb[2*k], Bb[2*k+1]);
            upd(c00[0], cbase,     best0, sec0, idx0);
            upd(c00[1], cbase + 1, best0, sec0, idx0);
            upd(c00[2], cbase,     best1, sec1, idx1);
            upd(c00[3], cbase + 1, best1, sec1, idx1);
        }
    }

    // merge across quad
    #pragma unroll
    for (int off = 1; off <= 2; off <<= 1) {
        float ob = __shfl_xor_sync(0xffffffffu, best0, off);
        float os = __shfl_xor_sync(0xffffffffu, sec0,  off);
        int   oi = __shfl_xor_sync(0xffffffffu, idx0,  off);
        if (ob > best0 || (ob == best0 && oi < idx0)) {
            sec0 = fmaxf(best0, os); best0 = ob; idx0 = oi;
        } else sec0 = fmaxf(sec0, ob);

        float pb = __shfl_xor_sync(0xffffffffu, best1, off);
        float ps = __shfl_xor_sync(0xffffffffu, sec1,  off);
        int   pi = __shfl_xor_sync(0xffffffffu, idx1,  off);
        if (pb > best1 || (pb == best1 && pi < idx1)) {
            sec1 = fmaxf(best1, ps); best1 = pb; idx1 = pi;
        } else sec1 = fmaxf(sec1, pb);
    }

    if (q4 == 0) {
        const int row0 = blk * M_TILE + warp * 16 + (lane >> 2);
        const int row1 = row0 + 8;
        g_idx[row0] = idx0;
        g_idx[row1] = idx1;
        atomicAdd(&shist[idx0], 1);
        atomicAdd(&shist[idx1], 1);
        if (best0 - sec0 < EPS1) { int p = atomicAdd(&g_flagN, 1); g_flag[p] = row0; }
        if (best1 - sec1 < EPS1) { int p = atomicAdd(&g_flagN, 1); g_flag[p] = row1; }
    }
    __syncthreads();
    g_bh[tid * A_BLOCKS + blk] = shist[tid];
}

// ---------------- recheck: exact fp32 argmin, 16 flagged rows per block ------------
// grid=148 (one CTA/SM, ~wave-balanced). 512 threads = (row 0..15) x (chunk 0..31
// of 16 codes); 16 register accumulators. Fixed order -> deterministic; winner via
// order-encoded u64 atomicMax (ties -> lowest code index).
__global__ void __launch_bounds__(512, 1) recheck_kernel(const float* __restrict__ x,
                                                         const float* __restrict__ emb)
{
    extern __shared__ __align__(16) char smem[];
    float4* se4 = (float4*)(smem + RC_E);
    float4* sx4 = (float4*)(smem + RC_X);    // stride 17 float4 per row
    float*  sh  = (float*) (smem + RC_H);    // negated half norms
    unsigned long long* sres = (unsigned long long*)(smem + RC_R);

    const int tid = threadIdx.x;
    const int nflag = g_flagN;
    const int ntile = (nflag + R_ROWS - 1) / R_ROWS;
    if (blockIdx.x >= (unsigned)ntile) return;

    {
        const float4* e4 = (const float4*)emb;
        #pragma unroll 4
        for (int t = 0; t < 16; ++t) se4[tid + t * 512] = e4[tid + t * 512];
        sh[tid] = g_nhalf[tid];
    }

    for (int t = blockIdx.x; t < ntile; t += gridDim.x) {
        __syncthreads();
        if (tid < 256) {   // stage 16 rows (256 float4)
            int row = tid >> 4, grp = tid & 15;
            int fi = t * R_ROWS + row;
            int rid = g_flag[fi < nflag ? fi : 0];
            sx4[row * 17 + grp] = ((const float4*)x)[(size_t)rid * 16 + grp];
        }
        if (tid < R_ROWS) sres[tid] = 0ull;
        __syncthreads();

        const int row = tid & 15;
        const int c0 = (tid >> 4) * 16;      // chunk of 16 codes

        float acc[16];
        #pragma unroll
        for (int j = 0; j < 16; ++j) acc[j] = 0.f;

        #pragma unroll 4
        for (int q = 0; q < 16; ++q) {
            float4 xv = sx4[row * 17 + q];
            #pragma unroll
            for (int j = 0; j < 16; ++j) {
                float4 ev = se4[(c0 + j) * 16 + q];
                acc[j] += ev.x * xv.x + ev.y * xv.y + ev.z * xv.z + ev.w * xv.w;
            }
        }

        float best = -3.0e38f; int bi = 0;
        #pragma unroll
        for (int j = 0; j < 16; ++j) {
            float v = acc[j] + sh[c0 + j];   // sh is negated: add == subtract half
            if (v > best) { best = v; bi = c0 + j; }   // ascending j: first max
        }
        atomicMax(&sres[row], enc(best, bi));
        __syncthreads();

        if (tid < R_ROWS) {
            int fi = t * R_ROWS + tid;
            if (fi < nflag) {
                int rid = g_flag[fi];
                int bi2 = KCODES - 1 - (int)(sres[tid] & 0xffffffffull);
                int old = g_idx[rid];
                if (bi2 != old) {
                    g_idx[rid] = bi2;
                    const int b = rid >> 8;                  // 256 rows per block
                    atomicSub(&g_bh[old * A_BLOCKS + b], 1);
                    atomicAdd(&g_bh[bi2 * A_BLOCKS + b], 1);
                }
            }
        }
    }
}

// ---------------- scan1: per-cluster block-prefix, one warp per cluster ------------
__global__ void scan1_kernel()
{
    const int k = blockIdx.x;
    const int lane = threadIdx.x;
    const int4* src = (const int4*)(g_bh + k * A_BLOCKS + lane * 32);
    int4 v[8];
    int s = 0;
    #pragma unroll
    for (int j = 0; j < 8; ++j) { v[j] = src[j]; s += v[j].x + v[j].y + v[j].z + v[j].w; }
    int run = s;
    #pragma unroll
    for (int off = 1; off < 32; off <<= 1) {
        int t = __shfl_up_sync(0xffffffffu, run, off);
        if (lane >= off) run += t;
    }
    int c = run - s;
    int4* dst = (int4*)(g_bhoff + k * A_BLOCKS + lane * 32);
    #pragma unroll
    for (int j = 0; j < 8; ++j) {
        int4 o;
        o.x = c; c += v[j].x;
        o.y = c; c += v[j].y;
        o.z = c; c += v[j].z;
        o.w = c; c += v[j].w;
        dst[j] = o;
    }
    if (lane == 31) g_tot[k] = run;
}

// ---------------- scatter: stable counting sort + local global-offset scan ---------
__global__ void scatter_kernel()
{
    __shared__ int scur[KCODES];
    const int b = blockIdx.x;          // 1024 blocks x 256 rows
    const int lane = threadIdx.x;

    // local exclusive scan of g_tot: lane handles clusters [lane*16, lane*16+16)
    int tv[16];
    {
        const int4* tp = (const int4*)(g_tot + lane * 16);
        int4 t0 = tp[0], t1 = tp[1], t2 = tp[2], t3 = tp[3];
        tv[0]=t0.x; tv[1]=t0.y; tv[2]=t0.z; tv[3]=t0.w;
        tv[4]=t1.x; tv[5]=t1.y; tv[6]=t1.z; tv[7]=t1.w;
        tv[8]=t2.x; tv[9]=t2.y; tv[10]=t2.z; tv[11]=t2.w;
        tv[12]=t3.x; tv[13]=t3.y; tv[14]=t3.z; tv[15]=t3.w;
    }
    int lsum = 0;
    #pragma unroll
    for (int j = 0; j < 16; ++j) lsum += tv[j];
    int run = lsum;
    #pragma unroll
    for (int off = 1; off < 32; off <<= 1) {
        int t = __shfl_up_sync(0xffffffffu, run, off);
        if (lane >= off) run += t;
    }
    int c = run - lsum;                 // exclusive prefix at cluster lane*16
    #pragma unroll
    for (int j = 0; j < 16; ++j) {
        int k = lane * 16 + j;
        scur[k] = c + g_bhoff[k * A_BLOCKS + b];
        if (b == 0) g_off[k] = c;       // publish for cluster_kernel
        c += tv[j];
    }
    __syncwarp();

    const int base = b * 256;
    int pk[8];
    #pragma unroll
    for (int j = 0; j < 8; ++j) pk[j] = g_idx[base + j * 32 + lane];
    __syncwarp();
    #pragma unroll 1
    for (int j = 0; j < 8; ++j) {
        int n = base + j * 32 + lane;
        int k = pk[j];
        unsigned m = __match_any_sync(0xffffffffu, k);
        unsigned below = m & ((1u << lane) - 1u);
        int pos = scur[k] + __popc(below);
        __syncwarp();
        if (below == 0) scur[k] += __popc(m);
        __syncwarp();
        g_sorted[pos] = n;
    }
}

// ---------------- cluster: per-cluster sum (16 fixed chains) + EMA ----------------
__global__ void __launch_bounds__(1024, 1) cluster_kernel(
    const float* __restrict__ x,
    const float* __restrict__ count_in,
    const float* __restrict__ sum_embed)
{
    __shared__ float part[16][DDIM];
    const int k = blockIdx.x;
    const int d = threadIdx.x & 63;
    const int s = threadIdx.x >> 6;
    const int start = g_off[k];
    const int cnt   = g_tot[k];
    const int q  = (cnt + 15) >> 4;
    const int i0 = s * q;
    int i1 = i0 + q; if (i1 > cnt) i1 = cnt;

    float a0 = 0.f, a1 = 0.f, a2 = 0.f, a3 = 0.f;
    int i = i0;
    for (; i + 4 <= i1; i += 4) {
        int r0 = g_sorted[start + i];
        int r1 = g_sorted[start + i + 1];
        int r2 = g_sorted[start + i + 2];
        int r3 = g_sorted[start + i + 3];
        a0 += x[(size_t)r0 * 64 + d];
        a1 += x[(size_t)r1 * 64 + d];
        a2 += x[(size_t)r2 * 64 + d];
        a3 += x[(size_t)r3 * 64 + d];
    }
    for (; i < i1; ++i) a0 += x[(size_t)g_sorted[start + i] * 64 + d];
    part[s][d] = (a0 + a1) + (a2 + a3);
    __syncthreads();

    if (s == 0) {
        float sum = (((part[0][d] + part[1][d]) + (part[2][d] + part[3][d]))
                  +  ((part[4][d] + part[5][d]) + (part[6][d] + part[7][d])))
                  + (((part[8][d] + part[9][d]) + (part[10][d] + part[11][d]))
                  +  ((part[12][d] + part[13][d]) + (part[14][d] + part[15][d])));
        float sev = sum_embed[k * 64 + d];
        float ns  = sev + 0.01f * (sum - sev);
        float cv  = count_in[k];
        float cn  = cv + 0.01f * ((float)cnt - cv);
        if (cn < 1.0f) cn = 1.0f;
        g_code[k * 64 + d] = ns / cn;
    }
}

// ---------------- gather: exact-size, one float4 per thread ----------------
__global__ void gather_kernel(float4* __restrict__ out)
{
    const int id = blockIdx.x * blockDim.x + threadIdx.x;   // 0 .. NTOK*16-1
    const int row = id >> 4;
    const int col = id & 15;
    const int k = g_idx[row];
    out[id] = ((const float4*)g_code)[k * 16 + col];
}

// ---------------- launch ----------------
extern "C" void kernel_launch(void* const* d_in, const int* in_sizes, int n_in,
                              void* d_out, int out_size)
{
    (void)in_sizes; (void)n_in; (void)out_size;
    const float* x         = (const float*)d_in[0];
    const float* emb       = (const float*)d_in[1];
    const float* count     = (const float*)d_in[2];
    const float* sum_embed = (const float*)d_in[3];

    cudaFuncSetAttribute(assign_mma,
                         cudaFuncAttributeMaxDynamicSharedMemorySize, SM_BYTES);
    cudaFuncSetAttribute(recheck_kernel,
                         cudaFuncAttributeMaxDynamicSharedMemorySize, RC_BYTES);

    prep_kernel<<<KCODES, 64>>>(emb);               // #1
    assign_mma<<<A_CTAS, 512, SM_BYTES>>>(x);       // #2
    recheck_kernel<<<148, 512, RC_BYTES>>>(x, emb); // #3
    scan1_kernel<<<KCODES, 32>>>();                 // #4  <-- ncu capture slot
    scatter_kernel<<<A_BLOCKS, 32>>>();
    cluster_kernel<<<KCODES, 1024>>>(x, count, sum_embed);
    gather_kernel<<<NTOK * 16 / 256, 256>>>((float4*)d_out);
}